// round 1
// baseline (speedup 1.0000x reference)
#include <cuda_runtime.h>
#include <cstdint>

// Problem constants (fixed by the reference: B=16, N=2048, D=64, fp32)
#define B_  16
#define N_  2048
#define D_  64
#define BM  128          // rows per CTA tile
#define BK  16           // k-slice per iteration
#define AS_STRIDE (BM + 4)   // 132 floats = 528B rows -> 16B aligned, conflict-reduced

typedef unsigned long long ull;

// Packed fp32x2 FMA (Blackwell FFMA2) — d = a*b + d, lane-wise on 2 floats
__device__ __forceinline__ void ffma2(ull &d, ull a, ull b) {
    asm("fma.rn.f32x2 %0, %1, %2, %0;" : "+l"(d) : "l"(a), "l"(b));
}
__device__ __forceinline__ ull dup2(float x) {
    ull r;
    asm("mov.b64 %0, {%1, %1};" : "=l"(r) : "f"(x));
    return r;
}
__device__ __forceinline__ float f2lo(ull v) { return __uint_as_float((unsigned)(v & 0xffffffffull)); }
__device__ __forceinline__ float f2hi(ull v) { return __uint_as_float((unsigned)(v >> 32)); }

__global__ __launch_bounds__(256, 2)
void gcn_agg_kernel(const float* __restrict__ nodes,
                    const float* __restrict__ edges,
                    float* __restrict__ out)
{
    __shared__ float As[BK][AS_STRIDE];  // A tile, k-major (transposed)
    __shared__ float Xs[BK][D_];         // X tile, k-major (natural)
    __shared__ float Rs[BM];             // row sums of A (incl. +I)

    const int tid = threadIdx.x;
    const int i0  = blockIdx.x * BM;     // global row base of this tile
    const int b   = blockIdx.y;

    // compute mapping: 16 column-groups x 16 row-groups
    const int cg = tid & 15;             // cols cg*4 .. cg*4+3
    const int rg = tid >> 4;             // rows rg*8 .. rg*8+7

    const float* __restrict__ eb = edges + (size_t)b * N_ * N_;
    const float* __restrict__ nb = nodes + (size_t)b * N_ * D_;

    // accumulators: acc[p][c] = (row rg*8+2p, row rg*8+2p+1) at col cg*4+c
    ull acc[4][4];
    #pragma unroll
    for (int p = 0; p < 4; ++p)
        #pragma unroll
        for (int c = 0; c < 4; ++c) acc[p][c] = 0ull;

    // fused row-sum partials (threads 0..127 own row == tid)
    float rs0 = 0.f, rs1 = 0.f, rs2 = 0.f, rs3 = 0.f;

    // ---- tile load helpers ----
    // A: 512 float4s per tile; thread handles v = tid and v = tid+256
    auto loadA = [&](int k0, int v) -> float4 {
        const int row = v >> 2;          // 0..127
        const int kk4 = v & 3;           // which float4 within the 16-wide k slice
        float4 g = *(const float4*)(eb + (size_t)(i0 + row) * N_ + (k0 + kk4 * 4));
        // fuse A = edges + I
        const int ig = i0 + row, jg = k0 + kk4 * 4;
        if (ig == jg + 0) g.x += 1.0f;
        if (ig == jg + 1) g.y += 1.0f;
        if (ig == jg + 2) g.z += 1.0f;
        if (ig == jg + 3) g.w += 1.0f;
        return g;
    };
    auto storeA = [&](int v, float4 g) {
        const int row = v >> 2;
        const int kk4 = v & 3;
        As[kk4 * 4 + 0][row] = g.x;
        As[kk4 * 4 + 1][row] = g.y;
        As[kk4 * 4 + 2][row] = g.z;
        As[kk4 * 4 + 3][row] = g.w;
    };
    auto loadX = [&](int k0) -> float4 {
        const int kk = tid >> 4;         // 0..15
        const int d4 = tid & 15;         // float4 index within the 64-wide row
        return *(const float4*)(nb + (size_t)(k0 + kk) * D_ + d4 * 4);
    };
    auto storeX = [&](float4 g) {
        const int kk = tid >> 4;
        const int d4 = tid & 15;
        *(float4*)&Xs[kk][d4 * 4] = g;
    };

    // ---- prologue: load tile 0 ----
    {
        float4 a0 = loadA(0, tid);
        float4 a1 = loadA(0, tid + 256);
        float4 x0 = loadX(0);
        storeA(tid, a0);
        storeA(tid + 256, a1);
        storeX(x0);
    }
    __syncthreads();

    const int NTILES = N_ / BK;          // 128
    for (int kt = 0; kt < NTILES; ++kt) {
        // register prefetch of next tile (hides DRAM latency under compute)
        float4 na0, na1, nx;
        const bool more = (kt + 1 < NTILES);
        if (more) {
            const int k0n = (kt + 1) * BK;
            na0 = loadA(k0n, tid);
            na1 = loadA(k0n, tid + 256);
            nx  = loadX(k0n);
        }

        // fused row-sum: thread t (<128) owns row t; A tile already includes +I
        if (tid < BM) {
            #pragma unroll
            for (int kk = 0; kk < BK; kk += 4) {
                rs0 += As[kk + 0][tid];
                rs1 += As[kk + 1][tid];
                rs2 += As[kk + 2][tid];
                rs3 += As[kk + 3][tid];
            }
        }

        // main FFMA2 loop
        #pragma unroll
        for (int kk = 0; kk < BK; ++kk) {
            // 4 natural row-pairs (16B-aligned: 528*kk + 32*rg bytes)
            ulonglong2 a01 = *(const ulonglong2*)&As[kk][rg * 8];
            ulonglong2 a23 = *(const ulonglong2*)&As[kk][rg * 8 + 4];
            float4 xv = *(const float4*)&Xs[kk][cg * 4];
            ull x0 = dup2(xv.x), x1 = dup2(xv.y), x2 = dup2(xv.z), x3 = dup2(xv.w);

            ffma2(acc[0][0], a01.x, x0); ffma2(acc[0][1], a01.x, x1);
            ffma2(acc[0][2], a01.x, x2); ffma2(acc[0][3], a01.x, x3);
            ffma2(acc[1][0], a01.y, x0); ffma2(acc[1][1], a01.y, x1);
            ffma2(acc[1][2], a01.y, x2); ffma2(acc[1][3], a01.y, x3);
            ffma2(acc[2][0], a23.x, x0); ffma2(acc[2][1], a23.x, x1);
            ffma2(acc[2][2], a23.x, x2); ffma2(acc[2][3], a23.x, x3);
            ffma2(acc[3][0], a23.y, x0); ffma2(acc[3][1], a23.y, x1);
            ffma2(acc[3][2], a23.y, x2); ffma2(acc[3][3], a23.y, x3);
        }
        __syncthreads();

        if (more) {
            storeA(tid, na0);
            storeA(tid + 256, na1);
            storeX(nx);
        }
        __syncthreads();
    }

    // ---- epilogue: publish row sums, divide, store ----
    if (tid < BM) Rs[tid] = (rs0 + rs1) + (rs2 + rs3);
    __syncthreads();

    float* __restrict__ ob = out + (size_t)b * N_ * D_ + (size_t)i0 * D_;
    #pragma unroll
    for (int p = 0; p < 4; ++p) {
        const int r0 = rg * 8 + 2 * p;
        const int r1 = r0 + 1;
        const float d0 = Rs[r0];
        const float d1 = Rs[r1];
        // denom >= 1 for this problem (A includes self-loop), guard mirrors
        // reference's NaN->0 on 0/0 rows anyway.
        const float inv0 = (d0 != 0.0f) ? (1.0f / d0) : 0.0f;
        const float inv1 = (d1 != 0.0f) ? (1.0f / d1) : 0.0f;

        float4 o0, o1;
        o0.x = f2lo(acc[p][0]) * inv0;
        o0.y = f2lo(acc[p][1]) * inv0;
        o0.z = f2lo(acc[p][2]) * inv0;
        o0.w = f2lo(acc[p][3]) * inv0;
        o1.x = f2hi(acc[p][0]) * inv1;
        o1.y = f2hi(acc[p][1]) * inv1;
        o1.z = f2hi(acc[p][2]) * inv1;
        o1.w = f2hi(acc[p][3]) * inv1;

        *(float4*)(ob + (size_t)r0 * D_ + cg * 4) = o0;
        *(float4*)(ob + (size_t)r1 * D_ + cg * 4) = o1;
    }
}

extern "C" void kernel_launch(void* const* d_in, const int* in_sizes, int n_in,
                              void* d_out, int out_size)
{
    // metadata order: nodes (B*N*D = 2,097,152), edges (B*N*N = 67,108,864).
    // Select defensively by size in case of ordering surprises.
    const float* nodes = (const float*)d_in[0];
    const float* edges = (const float*)d_in[1];
    if (n_in >= 2 && in_sizes[0] > in_sizes[1]) {
        nodes = (const float*)d_in[1];
        edges = (const float*)d_in[0];
    }

    dim3 grid(N_ / BM, B_);   // 16 x 16 = 256 CTAs
    gcn_agg_kernel<<<grid, 256>>>(nodes, edges, (float*)d_out);
}

// round 4
// speedup vs baseline: 2.1328x; 2.1328x over previous
#include <cuda_runtime.h>
#include <cuda_bf16.h>
#include <cstdint>

// ---------------- problem constants ----------------
#define B_   16
#define N_   2048
#define D_   64
#define BM   128
#define BK   32
#define NT   (N_/BK)     // 64 k-tiles
#define AROW 40          // A smem row stride in bf16 elements (80B, conflict-free)

// X pre-converted to mma B-fragment layout:
// [b][ks(128)][j(8)][lane(32)] -> uint4 {bhi0, bhi1, blo0, blo1}
__device__ uint4 g_xfrag[(size_t)B_ * 128 * 8 * 32];

// ---------------- helpers ----------------
__device__ __forceinline__ uint32_t smem_u32(const void* p) {
    uint32_t a;
    asm("{ .reg .u64 t; cvta.to.shared.u64 t, %1; cvt.u32.u64 %0, t; }" : "=r"(a) : "l"(p));
    return a;
}
__device__ __forceinline__ uint32_t packbf(__nv_bfloat16 a, __nv_bfloat16 b) {
    uint16_t ua = __bfloat16_as_ushort(a), ub = __bfloat16_as_ushort(b);
    return (uint32_t)ua | ((uint32_t)ub << 16);
}
__device__ __forceinline__ void ldsm4(uint32_t* r, uint32_t addr) {
    asm volatile("ldmatrix.sync.aligned.m8n8.x4.shared.b16 {%0,%1,%2,%3}, [%4];"
        : "=r"(r[0]), "=r"(r[1]), "=r"(r[2]), "=r"(r[3]) : "r"(addr));
}
__device__ __forceinline__ void mma_bf16(float* d, const uint32_t* a, uint32_t b0, uint32_t b1) {
    asm volatile(
        "mma.sync.aligned.m16n8k16.row.col.f32.bf16.bf16.f32 "
        "{%0,%1,%2,%3}, {%4,%5,%6,%7}, {%8,%9}, {%0,%1,%2,%3};"
        : "+f"(d[0]), "+f"(d[1]), "+f"(d[2]), "+f"(d[3])
        : "r"(a[0]), "r"(a[1]), "r"(a[2]), "r"(a[3]), "r"(b0), "r"(b1));
}

// ---------------- kernel 1: X -> bf16 hi/lo B-fragments ----------------
__global__ __launch_bounds__(256)
void xfrag_kernel(const float* __restrict__ nodes) {
    const int u    = blockIdx.x * 8 + (threadIdx.x >> 5);  // (b, ks, j) unit
    const int lane = threadIdx.x & 31;
    const int b    = u >> 10;
    const int rem  = u & 1023;
    const int ks   = rem >> 3;
    const int j    = rem & 7;

    const int k0 = ks * 16 + 2 * (lane & 3);
    const int n  = j * 8 + (lane >> 2);
    const float* nb = nodes + (size_t)b * N_ * D_;

    float x0 = nb[(size_t)(k0 + 0) * D_ + n];
    float x1 = nb[(size_t)(k0 + 1) * D_ + n];
    float x2 = nb[(size_t)(k0 + 8) * D_ + n];
    float x3 = nb[(size_t)(k0 + 9) * D_ + n];

    __nv_bfloat16 h0 = __float2bfloat16_rn(x0), h1 = __float2bfloat16_rn(x1);
    __nv_bfloat16 h2 = __float2bfloat16_rn(x2), h3 = __float2bfloat16_rn(x3);
    __nv_bfloat16 l0 = __float2bfloat16_rn(x0 - __bfloat162float(h0));
    __nv_bfloat16 l1 = __float2bfloat16_rn(x1 - __bfloat162float(h1));
    __nv_bfloat16 l2 = __float2bfloat16_rn(x2 - __bfloat162float(h2));
    __nv_bfloat16 l3 = __float2bfloat16_rn(x3 - __bfloat162float(h3));

    uint4 o;
    o.x = packbf(h0, h1);
    o.y = packbf(h2, h3);
    o.z = packbf(l0, l1);
    o.w = packbf(l2, l3);
    g_xfrag[(size_t)u * 32 + lane] = o;
}

// ---------------- kernel 2: main mma GEMM + rowsum + divide ----------------
__global__ __launch_bounds__(256, 2)
void gcn_mma(const float* __restrict__ edges, float* __restrict__ out) {
    __shared__ uint16_t As[2][2][BM * AROW];   // [stage][hi/lo][row*40] = 40 KB
    __shared__ float rsum[BM][2];
    __shared__ float inv[BM];

    const int tid  = threadIdx.x;
    const int lane = tid & 31;
    const int w    = tid >> 5;
    const int i0   = blockIdx.x * BM;
    const int b    = blockIdx.y;

    const int wm = (w & 3) * 32;               // warp M offset (0..96)
    const int wn = (w >> 2) * 32;              // warp N offset (0 or 32)
    const int j0 = wn >> 3;                    // first n8 block index

    const float* __restrict__ eb = edges + (size_t)b * N_ * N_;
    const uint4* __restrict__ xb = g_xfrag + (size_t)b * 128 * 8 * 32;

    // A loader mapping: thread owns (row, k-half of 16)
    const int lrow = tid >> 1;
    const int lkh  = tid & 1;

    // ldmatrix lane constants
    const int lm_row = lane & 15;
    const int lm_kb  = (lane >> 4) * 16;       // byte offset for k 0-7 / 8-15

    float acc[2][4][4];
    #pragma unroll
    for (int mi = 0; mi < 2; ++mi)
        #pragma unroll
        for (int j = 0; j < 4; ++j)
            #pragma unroll
            for (int r = 0; r < 4; ++r) acc[mi][j][r] = 0.f;

    float rs = 0.f;
    float4 pf[4];

    // convert prefetched A regs -> smem buffer sb, tile index kt (for diag + rowsum)
    auto storeA = [&](int kt, int sb) {
        const int gr = i0 + lrow;
        uint32_t hu[8], lu[8];
        #pragma unroll
        for (int q = 0; q < 4; ++q) {
            float4 v = pf[q];
            const int gk = kt * BK + lkh * 16 + q * 4;
            if (gr == gk + 0) v.x += 1.f;
            if (gr == gk + 1) v.y += 1.f;
            if (gr == gk + 2) v.z += 1.f;
            if (gr == gk + 3) v.w += 1.f;
            rs += (v.x + v.y) + (v.z + v.w);
            __nv_bfloat16 hx = __float2bfloat16_rn(v.x), hy = __float2bfloat16_rn(v.y);
            __nv_bfloat16 hz = __float2bfloat16_rn(v.z), hw = __float2bfloat16_rn(v.w);
            __nv_bfloat16 lx = __float2bfloat16_rn(v.x - __bfloat162float(hx));
            __nv_bfloat16 ly = __float2bfloat16_rn(v.y - __bfloat162float(hy));
            __nv_bfloat16 lz = __float2bfloat16_rn(v.z - __bfloat162float(hz));
            __nv_bfloat16 lw = __float2bfloat16_rn(v.w - __bfloat162float(hw));
            hu[q * 2 + 0] = packbf(hx, hy);
            hu[q * 2 + 1] = packbf(hz, hw);
            lu[q * 2 + 0] = packbf(lx, ly);
            lu[q * 2 + 1] = packbf(lz, lw);
        }
        const int e0 = lrow * AROW + lkh * 16;
        *(uint4*)&As[sb][0][e0]     = make_uint4(hu[0], hu[1], hu[2], hu[3]);
        *(uint4*)&As[sb][0][e0 + 8] = make_uint4(hu[4], hu[5], hu[6], hu[7]);
        *(uint4*)&As[sb][1][e0]     = make_uint4(lu[0], lu[1], lu[2], lu[3]);
        *(uint4*)&As[sb][1][e0 + 8] = make_uint4(lu[4], lu[5], lu[6], lu[7]);
    };

    // ---- prologue: tile 0 ----
    #pragma unroll
    for (int q = 0; q < 4; ++q)
        pf[q] = *(const float4*)(eb + (size_t)(i0 + lrow) * N_ + lkh * 16 + q * 4);
    storeA(0, 0);
    __syncthreads();

    // B fragment double buffer; preload global kstep 0
    uint4 bfr[2][4];
    #pragma unroll
    for (int j = 0; j < 4; ++j)
        bfr[0][j] = xb[(size_t)(0 * 8 + j0 + j) * 32 + lane];

    for (int t = 0; t < NT; ++t) {
        const int sbuf = t & 1;
        // prefetch A tile t+1 (global)
        if (t + 1 < NT) {
            #pragma unroll
            for (int q = 0; q < 4; ++q)
                pf[q] = *(const float4*)(eb + (size_t)(i0 + lrow) * N_ +
                                         (t + 1) * BK + lkh * 16 + q * 4);
        }
        #pragma unroll
        for (int ks = 0; ks < 2; ++ks) {
            const int gks = t * 2 + ks;
            const int p = gks & 1;
            // prefetch next kstep's B fragments
            if (gks + 1 < 2 * NT) {
                #pragma unroll
                for (int j = 0; j < 4; ++j)
                    bfr[p ^ 1][j] = xb[(size_t)((gks + 1) * 8 + j0 + j) * 32 + lane];
            }
            // A fragments (hi and lo) via ldmatrix
            uint32_t ah[2][4], al[2][4];
            const uint32_t kboff = (uint32_t)(ks * 32 + lm_kb);
            #pragma unroll
            for (int mi = 0; mi < 2; ++mi) {
                const uint32_t roff = (uint32_t)(wm + mi * 16 + lm_row) * (AROW * 2);
                ldsm4(ah[mi], smem_u32(&As[sbuf][0][0]) + roff + kboff);
                ldsm4(al[mi], smem_u32(&As[sbuf][1][0]) + roff + kboff);
            }
            // 24 mma: hi*hi + hi*lo + lo*hi
            #pragma unroll
            for (int mi = 0; mi < 2; ++mi)
                #pragma unroll
                for (int j = 0; j < 4; ++j) {
                    const uint4 bv = bfr[p][j];
                    mma_bf16(acc[mi][j], ah[mi], bv.x, bv.y);
                    mma_bf16(acc[mi][j], ah[mi], bv.z, bv.w);
                    mma_bf16(acc[mi][j], al[mi], bv.x, bv.y);
                }
        }
        // store prefetched tile into the other buffer
        if (t + 1 < NT) storeA(t + 1, (t + 1) & 1);
        __syncthreads();
    }

    // ---- rowsum reduce + divide + store ----
    rsum[lrow][lkh] = rs;
    __syncthreads();
    if (tid < BM) {
        const float s = rsum[tid][0] + rsum[tid][1];
        inv[tid] = (s != 0.f) ? (1.0f / s) : 0.0f;
    }
    __syncthreads();

    float* __restrict__ ob = out + ((size_t)b * N_ + i0) * D_;
    #pragma unroll
    for (int mi = 0; mi < 2; ++mi) {
        const int r0 = wm + mi * 16 + (lane >> 2);
        const int r1 = r0 + 8;
        const float v0 = inv[r0];
        const float v1 = inv[r1];
        #pragma unroll
        for (int j = 0; j < 4; ++j) {
            const int c = wn + j * 8 + (lane & 3) * 2;
            float2 o0 = {acc[mi][j][0] * v0, acc[mi][j][1] * v0};
            float2 o1 = {acc[mi][j][2] * v1, acc[mi][j][3] * v1};
            *(float2*)(ob + (size_t)r0 * D_ + c) = o0;
            *(float2*)(ob + (size_t)r1 * D_ + c) = o1;
        }
    }
}

// ---------------- launcher ----------------
extern "C" void kernel_launch(void* const* d_in, const int* in_sizes, int n_in,
                              void* d_out, int out_size)
{
    const float* nodes = (const float*)d_in[0];
    const float* edges = (const float*)d_in[1];
    if (n_in >= 2 && in_sizes[0] > in_sizes[1]) {
        nodes = (const float*)d_in[1];
        edges = (const float*)d_in[0];
    }

    // 16384 warp-units, 8 warps per block
    xfrag_kernel<<<2048, 256>>>(nodes);
    gcn_mma<<<dim3(N_ / BM, B_), 256>>>(edges, (float*)d_out);
}